// round 14
// baseline (speedup 1.0000x reference)
#include <cuda_runtime.h>
#include <cuda_fp16.h>
#include <cstdint>

#define N_ROWS 65536
#define S_DIM  128
#define DIN    512
#define H_DIM  1024
#define DOUT   256

#define LO_SCALE 2048.0f
#define LO_INV   4.8828125e-4f   // 1/2048

// ---------------- device scratch (static module memory; no runtime alloc) ----------------
__device__ float g_u[N_ROWS];
__device__ float g_G[S_DIM * S_DIM];
__device__ float g_t[S_DIM];
__device__ float g_v[H_DIM];
__device__ float g_c;
__device__ float g_wp[S_DIM];
__device__ __half g_W1t_hi[H_DIM * DIN];   // [n][k] K-major, fp16 hi
__device__ __half g_W1t_lo[H_DIM * DIN];   // fp16 residual * 2048
__device__ __half g_d1_hi[(size_t)N_ROWS * DIN];  // 64 MB, fp16 hi of d1

// ---------------- PTX helpers (plain PTX only; no 'a'-features) ----------------
__device__ __forceinline__ uint32_t smem_u32(const void* p) {
    uint32_t a;
    asm("{ .reg .u64 t; cvta.to.shared.u64 t, %1; cvt.u32.u64 %0, t; }" : "=r"(a) : "l"(p));
    return a;
}
__device__ __forceinline__ void cp_async16(uint32_t dst, const void* src) {
    asm volatile("cp.async.cg.shared.global [%0], [%1], 16;" :: "r"(dst), "l"(src));
}
#define CP_COMMIT() asm volatile("cp.async.commit_group;" ::: "memory")
#define CP_WAIT0()  asm volatile("cp.async.wait_group 0;" ::: "memory")
#define CP_WAIT1()  asm volatile("cp.async.wait_group 1;" ::: "memory")

__device__ __forceinline__ void ldsm_x4(uint32_t& r0, uint32_t& r1, uint32_t& r2, uint32_t& r3,
                                        uint32_t a) {
    asm volatile("ldmatrix.sync.aligned.m8n8.x4.shared.b16 {%0,%1,%2,%3}, [%4];"
                 : "=r"(r0), "=r"(r1), "=r"(r2), "=r"(r3) : "r"(a));
}
// fp32-accumulate fp16 MMA (main term)
__device__ __forceinline__ void mma16816f(float* c, const uint32_t* a, uint32_t b0, uint32_t b1) {
    asm volatile("mma.sync.aligned.m16n8k16.row.col.f32.f16.f16.f32 "
                 "{%0,%1,%2,%3}, {%4,%5,%6,%7}, {%8,%9}, {%0,%1,%2,%3};"
                 : "+f"(c[0]), "+f"(c[1]), "+f"(c[2]), "+f"(c[3])
                 : "r"(a[0]), "r"(a[1]), "r"(a[2]), "r"(a[3]), "r"(b0), "r"(b1));
}
// fp16-accumulate fp16 MMA (correction term)
__device__ __forceinline__ void mma16816h(uint32_t* c, const uint32_t* a, uint32_t b0, uint32_t b1) {
    asm volatile("mma.sync.aligned.m16n8k16.row.col.f16.f16.f16.f16 "
                 "{%0,%1}, {%2,%3,%4,%5}, {%6,%7}, {%0,%1};"
                 : "+r"(c[0]), "+r"(c[1])
                 : "r"(a[0]), "r"(a[1]), "r"(a[2]), "r"(a[3]), "r"(b0), "r"(b1));
}

// ---- packed f32x2 helpers (gt kernel) ----
__device__ __forceinline__ unsigned long long pack2(float x, float y) {
    unsigned long long r;
    asm("mov.b64 %0, {%1, %2};" : "=l"(r) : "f"(x), "f"(y));
    return r;
}
__device__ __forceinline__ unsigned long long fma2(unsigned long long a, unsigned long long b,
                                                   unsigned long long c) {
    unsigned long long d;
    asm("fma.rn.f32x2 %0, %1, %2, %3;" : "=l"(d) : "l"(a), "l"(b), "l"(c));
    return d;
}
__device__ __forceinline__ void unpack2(unsigned long long v, float& x, float& y) {
    asm("mov.b64 {%0, %1}, %2;" : "=f"(x), "=f"(y) : "l"(v));
}

// ============================================================
// prep: zero G/t, v = W2 @ w_deep, c = b2 . w_deep
// ============================================================
__global__ __launch_bounds__(256) void prep_kernel(const float* __restrict__ W2,
                                                   const float* __restrict__ b2,
                                                   const float* __restrict__ w_deep) {
    __shared__ float wd[DOUT];
    __shared__ float red[256];
    const int tid = threadIdx.x;
    for (int i = tid; i < S_DIM * S_DIM; i += 256) g_G[i] = 0.f;
    if (tid < S_DIM) g_t[tid] = 0.f;
    if (tid < DOUT) wd[tid] = w_deep[tid];
    __syncthreads();
    for (int j = tid; j < H_DIM; j += 256) {
        const float4* wr = (const float4*)&W2[(size_t)j * DOUT];
        const float4* wv = (const float4*)wd;
        float s = 0.f;
#pragma unroll
        for (int q = 0; q < DOUT / 4; q++) {
            float4 a = wr[q]; float4 b = wv[q];
            s += a.x * b.x + a.y * b.y + a.z * b.z + a.w * b.w;
        }
        g_v[j] = s;
    }
    float pc = (tid < DOUT) ? b2[tid] * wd[tid] : 0.f;
    red[tid] = pc;
    __syncthreads();
    for (int sd = 128; sd > 0; sd >>= 1) {
        if (tid < sd) red[tid] += red[tid + sd];
        __syncthreads();
    }
    if (tid == 0) g_c = red[0];
}

// ============================================================
// convert W1 [k][n] -> W1t hi/lo [n][k] fp16 split (tiled transpose, coalesced)
// ============================================================
__global__ __launch_bounds__(256) void convert_w1_kernel(const float* __restrict__ W1) {
    __shared__ float tile[32][33];
    const int k0 = blockIdx.x * 32, n0 = blockIdx.y * 32;
    const int tx = threadIdx.x & 31, ty = threadIdx.x >> 5;   // ty 0..7
#pragma unroll
    for (int r = 0; r < 4; r++) {
        const int k = ty + r * 8;
        tile[k][tx] = W1[(size_t)(k0 + k) * H_DIM + n0 + tx];
    }
    __syncthreads();
#pragma unroll
    for (int r = 0; r < 4; r++) {
        const int n = ty + r * 8;
        const float x = tile[tx][n];
        const __half h = __float2half_rn(x);
        const float l = (x - __half2float(h)) * LO_SCALE;
        g_W1t_hi[(size_t)(n0 + n) * DIN + k0 + tx] = h;
        g_W1t_lo[(size_t)(n0 + n) * DIN + k0 + tx] = __float2half_rn(l);
    }
}

// ============================================================
// convert d1 fp32 -> fp16 hi only (row-major preserved)
// ============================================================
__global__ __launch_bounds__(256) void convert_d1_kernel(const float* __restrict__ d1) {
    const size_t i = (size_t)blockIdx.x * 256 + threadIdx.x;   // x8 floats
    const float4 f0 = ((const float4*)d1)[2 * i];
    const float4 f1 = ((const float4*)d1)[2 * i + 1];
    const __half2 h0 = __floats2half2_rn(f0.x, f0.y);
    const __half2 h1 = __floats2half2_rn(f0.z, f0.w);
    const __half2 h2 = __floats2half2_rn(f1.x, f1.y);
    const __half2 h3 = __floats2half2_rn(f1.z, f1.w);
    ((uint4*)g_d1_hi)[i] = make_uint4(*(const uint32_t*)&h0, *(const uint32_t*)&h1,
                                      *(const uint32_t*)&h2, *(const uint32_t*)&h3);
}

// ============================================================
// mlp_mma: u[i] = relu(d1[i,:] @ W1 + b1) . v + c  via fp16 mma.sync
// M-tile 64, N-tile 128, K-chunk 32, 4 warps (2M x 2N), warp tile 32x64.
// 2-term split: AhBh (fp32-acc) + AhBl (fp16-acc, lo pre-scaled by 2048).
// 128 threads, ~51.5KB smem + launch_bounds(128,4) -> 4 CTAs/SM:
// four independent barrier domains per SM overlap sync/wait windows.
// b1/v read from global in the (rare) epilogue instead of smem staging.
// ============================================================
#define ROWB    80                       // 32 fp16 data (64B) + 16B pad
#define ATILE   (64 * ROWB)              // 5120 B
#define BTILE   (128 * ROWB)             // 10240 B
#define BUFSZ   (ATILE + 2 * BTILE)      // 25600 B: Ah, Bhi, Blo
#define OFF_US  (2 * BUFSZ)              // 51200
#define MLP_SMEM (OFF_US + 256)          // 51456 bytes -> 4 CTAs/SM

__device__ __forceinline__ void fill_chunk(uint32_t smBase, int buf, int rowBase, int idx,
                                           int tid) {
    const int nt = idx >> 4, kc = idx & 15;
    const int k0 = kc * 32;
    const int n0 = nt * 128;
    const uint32_t base = smBase + buf * BUFSZ;
    // A hi: 64 rows x 64B = 256 chunks (2 per thread)
#pragma unroll
    for (int p = 0; p < 2; p++) {
        const int ch = p * 128 + tid;
        const int row = ch >> 2, c = ch & 3;
        cp_async16(base + row * ROWB + c * 16,
                   g_d1_hi + (size_t)(rowBase + row) * DIN + k0 + c * 8);
    }
    // B hi+lo: 128 rows x 64B each = 512 chunks per split (4 per thread)
#pragma unroll
    for (int p = 0; p < 4; p++) {
        const int ch = p * 128 + tid;
        const int row = ch >> 2, c = ch & 3;
        const uint32_t d = base + ATILE + row * ROWB + c * 16;
        const size_t boff = (size_t)(n0 + row) * DIN + k0 + c * 8;
        cp_async16(d,         g_W1t_hi + boff);
        cp_async16(d + BTILE, g_W1t_lo + boff);
    }
}

__global__ __launch_bounds__(128, 4) void mlp_mma_kernel(const float* __restrict__ b1) {
    extern __shared__ char smem[];
    char* smemc = smem;
    const uint32_t sm = smem_u32(smem);
    const int tid = threadIdx.x;
    const int lane = tid & 31;
    const int w = tid >> 5;
    const int mw = w & 1;                  // M-warp: rows mw*32..+31
    const int nw = w >> 1;                 // N-warp: cols nw*64..+63
    const int rowBase = blockIdx.x * 64;

    float* u_s = (float*)(smemc + OFF_US);
    if (tid < 64) u_s[tid] = 0.f;

    float    cacc[2][8][4];                // main, fp32
    uint32_t c16[2][8][2];                 // correction, fp16x2 pairs
#pragma unroll
    for (int i = 0; i < 2; i++)
#pragma unroll
        for (int j = 0; j < 8; j++) {
#pragma unroll
            for (int r = 0; r < 4; r++) cacc[i][j][r] = 0.f;
            c16[i][j][0] = 0u; c16[i][j][1] = 0u;
        }

    fill_chunk(sm, 0, rowBase, 0, tid); CP_COMMIT();
    fill_chunk(sm, 1, rowBase, 1, tid); CP_COMMIT();

    for (int idx = 0; idx < 128; idx++) {
        if (idx >= 126) { CP_WAIT0(); } else { CP_WAIT1(); }
        __syncthreads();
        const uint32_t base = sm + (idx & 1) * BUFSZ;
        const uint32_t aBase = base + (mw * 32) * ROWB;
        const uint32_t bBase = base + ATILE + (nw * 64) * ROWB;
#pragma unroll
        for (int ks = 0; ks < 2; ks++) {
            const uint32_t aAddr = aBase + (lane & 15) * ROWB + ((lane >> 4) * 16) + ks * 32;
            uint32_t ah[2][4];
            ldsm_x4(ah[0][0], ah[0][1], ah[0][2], ah[0][3], aAddr);
            ldsm_x4(ah[1][0], ah[1][1], ah[1][2], ah[1][3], aAddr + 16 * ROWB);
            const uint32_t bAddr0 = bBase + ((lane & 7) + ((lane >> 4) << 3)) * ROWB
                                    + (((lane >> 3) & 1) * 16) + ks * 32;
#pragma unroll
            for (int jj = 0; jj < 4; jj++) {
                uint32_t bh[4], bl[4];
                ldsm_x4(bh[0], bh[1], bh[2], bh[3], bAddr0 + jj * 16 * ROWB);
                ldsm_x4(bl[0], bl[1], bl[2], bl[3], bAddr0 + jj * 16 * ROWB + BTILE);
#pragma unroll
                for (int i = 0; i < 2; i++) {
                    mma16816f(cacc[i][2 * jj],     ah[i], bh[0], bh[1]);
                    mma16816f(cacc[i][2 * jj + 1], ah[i], bh[2], bh[3]);
                    mma16816h(c16[i][2 * jj],      ah[i], bl[0], bl[1]);
                    mma16816h(c16[i][2 * jj + 1],  ah[i], bl[2], bl[3]);
                }
            }
        }
        __syncthreads();
        if (idx + 2 < 128) { fill_chunk(sm, idx & 1, rowBase, idx + 2, tid); CP_COMMIT(); }

        if ((idx & 15) == 15) {
            const int nt = idx >> 4;
#pragma unroll
            for (int i = 0; i < 2; i++) {
                float s0 = 0.f, s1 = 0.f;
#pragma unroll
                for (int j = 0; j < 8; j++) {
                    const int col = nt * 128 + nw * 64 + j * 8 + (lane & 3) * 2;
                    const float bb0 = b1[col],  bb1 = b1[col + 1];
                    const float vv0 = g_v[col], vv1 = g_v[col + 1];
                    const float2 cr01 = __half22float2(*(const __half2*)&c16[i][j][0]);
                    const float2 cr23 = __half22float2(*(const __half2*)&c16[i][j][1]);
                    const float h0 = cacc[i][j][0] + cr01.x * LO_INV + bb0;
                    const float h1 = cacc[i][j][1] + cr01.y * LO_INV + bb1;
                    const float h2 = cacc[i][j][2] + cr23.x * LO_INV + bb0;
                    const float h3 = cacc[i][j][3] + cr23.y * LO_INV + bb1;
                    s0 += fmaxf(h0, 0.f) * vv0 + fmaxf(h1, 0.f) * vv1;
                    s1 += fmaxf(h2, 0.f) * vv0 + fmaxf(h3, 0.f) * vv1;
                    cacc[i][j][0] = cacc[i][j][1] = cacc[i][j][2] = cacc[i][j][3] = 0.f;
                    c16[i][j][0] = 0u; c16[i][j][1] = 0u;
                }
                s0 += __shfl_xor_sync(0xffffffffu, s0, 1);
                s0 += __shfl_xor_sync(0xffffffffu, s0, 2);
                s1 += __shfl_xor_sync(0xffffffffu, s1, 1);
                s1 += __shfl_xor_sync(0xffffffffu, s1, 2);
                if ((lane & 3) == 0) {
                    const int row0 = mw * 32 + i * 16 + (lane >> 2);
                    atomicAdd(&u_s[row0], s0);
                    atomicAdd(&u_s[row0 + 8], s1);
                }
            }
        }
    }
    __syncthreads();
    if (tid < 64) g_u[rowBase + tid] = u_s[tid] + g_c;
}

// ============================================================
// gt: G = A^T A (128x128), t = A^T u. grid 256 x 256 thr.
// ============================================================
__global__ __launch_bounds__(256) void gt_kernel(const float* __restrict__ A) {
    __shared__ float As[32][132];
    __shared__ float u_s[32];
    const int tid = threadIdx.x;
    const int tx = tid & 15;
    const int ty = tid >> 4;

    unsigned long long acc[8][4];
#pragma unroll
    for (int i = 0; i < 8; i++)
#pragma unroll
        for (int j = 0; j < 4; j++) acc[i][j] = 0ull;
    float t_loc = 0.f;

    const int base = blockIdx.x * 256;
    for (int ch = 0; ch < 8; ch++) {
        const int r0 = base + ch * 32;
        __syncthreads();
#pragma unroll
        for (int rr = 0; rr < 4; rr++) {
            int row = (tid >> 5) + rr * 8;
            *(float4*)&As[row][(tid & 31) * 4] =
                *(const float4*)&A[(size_t)(r0 + row) * S_DIM + (tid & 31) * 4];
        }
        if (tid < 32) u_s[tid] = g_u[r0 + tid];
        __syncthreads();

#pragma unroll 4
        for (int r = 0; r < 32; r++) {
            float4 a0 = *(const float4*)&As[r][ty * 8];
            float4 a1 = *(const float4*)&As[r][ty * 8 + 4];
            unsigned long long a2[8];
            a2[0] = pack2(a0.x, a0.x); a2[1] = pack2(a0.y, a0.y);
            a2[2] = pack2(a0.z, a0.z); a2[3] = pack2(a0.w, a0.w);
            a2[4] = pack2(a1.x, a1.x); a2[5] = pack2(a1.y, a1.y);
            a2[6] = pack2(a1.z, a1.z); a2[7] = pack2(a1.w, a1.w);
            const ulonglong2* bp = (const ulonglong2*)&As[r][tx * 8];
            ulonglong2 bb0 = bp[0];
            ulonglong2 bb1 = bp[1];
            unsigned long long bv[4] = {bb0.x, bb0.y, bb1.x, bb1.y};
#pragma unroll
            for (int i = 0; i < 8; i++)
#pragma unroll
                for (int j = 0; j < 4; j++)
                    acc[i][j] = fma2(a2[i], bv[j], acc[i][j]);
        }
        if (tid < 128) {
#pragma unroll 8
            for (int r = 0; r < 32; r++) t_loc += As[r][tid] * u_s[r];
        }
    }

#pragma unroll
    for (int i = 0; i < 8; i++)
#pragma unroll
        for (int j = 0; j < 4; j++) {
            float lo, hi;
            unpack2(acc[i][j], lo, hi);
            atomicAdd(&g_G[(ty * 8 + i) * S_DIM + tx * 8 + 2 * j], lo);
            atomicAdd(&g_G[(ty * 8 + i) * S_DIM + tx * 8 + 2 * j + 1], hi);
        }
    if (tid < 128) atomicAdd(&g_t[tid], t_loc);
}

// ============================================================
// solve: G y = t via Jacobi (rho ~ 0.09 for this Wishart), 24 iters.
// wp = w_struct - y.
// ============================================================
__global__ __launch_bounds__(128) void solve_kernel(const float* __restrict__ w_struct) {
    __shared__ float ys[S_DIM];
    const int tid = threadIdx.x;
    const float tv = g_t[tid];
    const float dinv = 1.0f / g_G[tid * S_DIM + tid];
    ys[tid] = tv * dinv;
    __syncthreads();
    const float* row = &g_G[tid * S_DIM];
    for (int it = 0; it < 24; it++) {
        float s = 0.f;
#pragma unroll 16
        for (int j = 0; j < S_DIM; j++) s += row[j] * ys[j];
        const float r = (tv - s) * dinv;
        __syncthreads();
        ys[tid] += r;
        __syncthreads();
    }
    g_wp[tid] = w_struct[tid] - ys[tid];
}

// ============================================================
// final: out[i] = u[i] + A[i,:] . wp
// ============================================================
__global__ __launch_bounds__(256) void final_kernel(const float* __restrict__ A,
                                                    float* __restrict__ out) {
    __shared__ float wp_s[S_DIM];
    const int tid = threadIdx.x;
    if (tid < S_DIM) wp_s[tid] = g_wp[tid];
    __syncthreads();
    const int i = blockIdx.x * 256 + tid;
    const float4* ar = (const float4*)&A[(size_t)i * S_DIM];
    float s = g_u[i];
#pragma unroll
    for (int q = 0; q < 32; q++) {
        float4 a = ar[q];
        s += a.x * wp_s[4 * q] + a.y * wp_s[4 * q + 1] +
             a.z * wp_s[4 * q + 2] + a.w * wp_s[4 * q + 3];
    }
    out[i] = s;
}

// ============================================================
extern "C" void kernel_launch(void* const* d_in, const int* in_sizes, int n_in,
                              void* d_out, int out_size) {
    const float* structured = (const float*)d_in[0];
    const float* d1         = (const float*)d_in[1];
    const float* W1         = (const float*)d_in[2];
    const float* b1         = (const float*)d_in[3];
    const float* W2         = (const float*)d_in[4];
    const float* b2         = (const float*)d_in[5];
    const float* w_struct   = (const float*)d_in[6];
    const float* w_deep     = (const float*)d_in[7];
    float* out = (float*)d_out;

    cudaFuncSetAttribute(mlp_mma_kernel, cudaFuncAttributeMaxDynamicSharedMemorySize,
                         MLP_SMEM);

    prep_kernel<<<1, 256>>>(W2, b2, w_deep);
    convert_w1_kernel<<<dim3(DIN / 32, H_DIM / 32), 256>>>(W1);
    convert_d1_kernel<<<(N_ROWS * DIN / 8) / 256, 256>>>(d1);
    mlp_mma_kernel<<<N_ROWS / 64, 128, MLP_SMEM>>>(b1);
    gt_kernel<<<N_ROWS / 256, 256>>>(structured);
    solve_kernel<<<1, 128>>>(w_struct);
    final_kernel<<<N_ROWS / 256, 256>>>(structured, out);
}

// round 15
// speedup vs baseline: 1.8831x; 1.8831x over previous
#include <cuda_runtime.h>
#include <cuda_fp16.h>
#include <cstdint>

#define N_ROWS 65536
#define S_DIM  128
#define DIN    512
#define H_DIM  1024
#define DOUT   256

#define LO_SCALE 2048.0f
#define LO_INV   4.8828125e-4f   // 1/2048

// ---------------- device scratch (static module memory; no runtime alloc) ----------------
__device__ float g_u[N_ROWS];
__device__ float g_G[S_DIM * S_DIM];
__device__ float g_t[S_DIM];
__device__ float g_v[H_DIM];
__device__ float g_c;
__device__ float g_wp[S_DIM];
__device__ __half g_W1t_hi[H_DIM * DIN];   // [n][k] K-major, fp16 hi
__device__ __half g_W1t_lo[H_DIM * DIN];   // fp16 residual * 2048
__device__ __half g_d1_hi[(size_t)N_ROWS * DIN];  // 64 MB, fp16 hi of d1

// ---------------- PTX helpers (plain PTX only; no 'a'-features) ----------------
__device__ __forceinline__ uint32_t smem_u32(const void* p) {
    uint32_t a;
    asm("{ .reg .u64 t; cvta.to.shared.u64 t, %1; cvt.u32.u64 %0, t; }" : "=r"(a) : "l"(p));
    return a;
}
__device__ __forceinline__ void cp_async16(uint32_t dst, const void* src) {
    asm volatile("cp.async.cg.shared.global [%0], [%1], 16;" :: "r"(dst), "l"(src));
}
#define CP_COMMIT() asm volatile("cp.async.commit_group;" ::: "memory")
#define CP_WAIT0()  asm volatile("cp.async.wait_group 0;" ::: "memory")
#define CP_WAIT1()  asm volatile("cp.async.wait_group 1;" ::: "memory")

__device__ __forceinline__ void ldsm_x4(uint32_t& r0, uint32_t& r1, uint32_t& r2, uint32_t& r3,
                                        uint32_t a) {
    asm volatile("ldmatrix.sync.aligned.m8n8.x4.shared.b16 {%0,%1,%2,%3}, [%4];"
                 : "=r"(r0), "=r"(r1), "=r"(r2), "=r"(r3) : "r"(a));
}
// fp32-accumulate fp16 MMA (main term)
__device__ __forceinline__ void mma16816f(float* c, const uint32_t* a, uint32_t b0, uint32_t b1) {
    asm volatile("mma.sync.aligned.m16n8k16.row.col.f32.f16.f16.f32 "
                 "{%0,%1,%2,%3}, {%4,%5,%6,%7}, {%8,%9}, {%0,%1,%2,%3};"
                 : "+f"(c[0]), "+f"(c[1]), "+f"(c[2]), "+f"(c[3])
                 : "r"(a[0]), "r"(a[1]), "r"(a[2]), "r"(a[3]), "r"(b0), "r"(b1));
}
// fp16-accumulate fp16 MMA (correction term)
__device__ __forceinline__ void mma16816h(uint32_t* c, const uint32_t* a, uint32_t b0, uint32_t b1) {
    asm volatile("mma.sync.aligned.m16n8k16.row.col.f16.f16.f16.f16 "
                 "{%0,%1}, {%2,%3,%4,%5}, {%6,%7}, {%0,%1};"
                 : "+r"(c[0]), "+r"(c[1])
                 : "r"(a[0]), "r"(a[1]), "r"(a[2]), "r"(a[3]), "r"(b0), "r"(b1));
}

// ---- packed f32x2 helpers (gt kernel) ----
__device__ __forceinline__ unsigned long long pack2(float x, float y) {
    unsigned long long r;
    asm("mov.b64 %0, {%1, %2};" : "=l"(r) : "f"(x), "f"(y));
    return r;
}
__device__ __forceinline__ unsigned long long fma2(unsigned long long a, unsigned long long b,
                                                   unsigned long long c) {
    unsigned long long d;
    asm("fma.rn.f32x2 %0, %1, %2, %3;" : "=l"(d) : "l"(a), "l"(b), "l"(c));
    return d;
}
__device__ __forceinline__ void unpack2(unsigned long long v, float& x, float& y) {
    asm("mov.b64 {%0, %1}, %2;" : "=f"(x), "=f"(y) : "l"(v));
}

// ============================================================
// prep: zero G/t, v = W2 @ w_deep, c = b2 . w_deep
// ============================================================
__global__ __launch_bounds__(256) void prep_kernel(const float* __restrict__ W2,
                                                   const float* __restrict__ b2,
                                                   const float* __restrict__ w_deep) {
    __shared__ float wd[DOUT];
    __shared__ float red[256];
    const int tid = threadIdx.x;
    for (int i = tid; i < S_DIM * S_DIM; i += 256) g_G[i] = 0.f;
    if (tid < S_DIM) g_t[tid] = 0.f;
    if (tid < DOUT) wd[tid] = w_deep[tid];
    __syncthreads();
    for (int j = tid; j < H_DIM; j += 256) {
        const float4* wr = (const float4*)&W2[(size_t)j * DOUT];
        const float4* wv = (const float4*)wd;
        float s = 0.f;
#pragma unroll
        for (int q = 0; q < DOUT / 4; q++) {
            float4 a = wr[q]; float4 b = wv[q];
            s += a.x * b.x + a.y * b.y + a.z * b.z + a.w * b.w;
        }
        g_v[j] = s;
    }
    float pc = (tid < DOUT) ? b2[tid] * wd[tid] : 0.f;
    red[tid] = pc;
    __syncthreads();
    for (int sd = 128; sd > 0; sd >>= 1) {
        if (tid < sd) red[tid] += red[tid + sd];
        __syncthreads();
    }
    if (tid == 0) g_c = red[0];
}

// ============================================================
// convert W1 [k][n] -> W1t hi/lo [n][k] fp16 split (tiled transpose, coalesced)
// ============================================================
__global__ __launch_bounds__(256) void convert_w1_kernel(const float* __restrict__ W1) {
    __shared__ float tile[32][33];
    const int k0 = blockIdx.x * 32, n0 = blockIdx.y * 32;
    const int tx = threadIdx.x & 31, ty = threadIdx.x >> 5;   // ty 0..7
#pragma unroll
    for (int r = 0; r < 4; r++) {
        const int k = ty + r * 8;
        tile[k][tx] = W1[(size_t)(k0 + k) * H_DIM + n0 + tx];
    }
    __syncthreads();
#pragma unroll
    for (int r = 0; r < 4; r++) {
        const int n = ty + r * 8;
        const float x = tile[tx][n];
        const __half h = __float2half_rn(x);
        const float l = (x - __half2float(h)) * LO_SCALE;
        g_W1t_hi[(size_t)(n0 + n) * DIN + k0 + tx] = h;
        g_W1t_lo[(size_t)(n0 + n) * DIN + k0 + tx] = __float2half_rn(l);
    }
}

// ============================================================
// convert d1 fp32 -> fp16 hi only (row-major preserved)
// ============================================================
__global__ __launch_bounds__(256) void convert_d1_kernel(const float* __restrict__ d1) {
    const size_t i = (size_t)blockIdx.x * 256 + threadIdx.x;   // x8 floats
    const float4 f0 = ((const float4*)d1)[2 * i];
    const float4 f1 = ((const float4*)d1)[2 * i + 1];
    const __half2 h0 = __floats2half2_rn(f0.x, f0.y);
    const __half2 h1 = __floats2half2_rn(f0.z, f0.w);
    const __half2 h2 = __floats2half2_rn(f1.x, f1.y);
    const __half2 h3 = __floats2half2_rn(f1.z, f1.w);
    ((uint4*)g_d1_hi)[i] = make_uint4(*(const uint32_t*)&h0, *(const uint32_t*)&h1,
                                      *(const uint32_t*)&h2, *(const uint32_t*)&h3);
}

// ============================================================
// mlp_mma: u[i] = relu(d1[i,:] @ W1 + b1) . v + c  via fp16 mma.sync
// M-tile 64, N-tile 128, K-chunk 32, 4 warps (2M x 2N), warp tile 32x64.
// 2-term split: AhBh (fp32-acc) + AhBl (fp16-acc, lo pre-scaled by 2048).
// 128 threads, ~58KB smem -> 3 CTAs/SM  (EXACT R13 winner — do not touch)
// ============================================================
#define ROWB    80                       // 32 fp16 data (64B) + 16B pad
#define ATILE   (64 * ROWB)              // 5120 B
#define BTILE   (128 * ROWB)             // 10240 B
#define BUFSZ   (ATILE + 2 * BTILE)      // 25600 B: Ah, Bhi, Blo
#define OFF_B1S (2 * BUFSZ)              // 51200
#define OFF_VS  (OFF_B1S + 4096)         // 55296
#define OFF_US  (OFF_VS + 4096)          // 59392
#define MLP_SMEM (OFF_US + 256)          // 59648 bytes -> 3 CTAs/SM

__device__ __forceinline__ void fill_chunk(uint32_t smBase, int buf, int rowBase, int idx,
                                           int tid) {
    const int nt = idx >> 4, kc = idx & 15;
    const int k0 = kc * 32;
    const int n0 = nt * 128;
    const uint32_t base = smBase + buf * BUFSZ;
    // A hi: 64 rows x 64B = 256 chunks (2 per thread)
#pragma unroll
    for (int p = 0; p < 2; p++) {
        const int ch = p * 128 + tid;
        const int row = ch >> 2, c = ch & 3;
        cp_async16(base + row * ROWB + c * 16,
                   g_d1_hi + (size_t)(rowBase + row) * DIN + k0 + c * 8);
    }
    // B hi+lo: 128 rows x 64B each = 512 chunks per split (4 per thread)
#pragma unroll
    for (int p = 0; p < 4; p++) {
        const int ch = p * 128 + tid;
        const int row = ch >> 2, c = ch & 3;
        const uint32_t d = base + ATILE + row * ROWB + c * 16;
        const size_t boff = (size_t)(n0 + row) * DIN + k0 + c * 8;
        cp_async16(d,         g_W1t_hi + boff);
        cp_async16(d + BTILE, g_W1t_lo + boff);
    }
}

__global__ __launch_bounds__(128) void mlp_mma_kernel(const float* __restrict__ b1) {
    extern __shared__ char smem[];
    char* smemc = smem;
    const uint32_t sm = smem_u32(smem);
    const int tid = threadIdx.x;
    const int lane = tid & 31;
    const int w = tid >> 5;
    const int mw = w & 1;                  // M-warp: rows mw*32..+31
    const int nw = w >> 1;                 // N-warp: cols nw*64..+63
    const int rowBase = blockIdx.x * 64;

    float* b1_s = (float*)(smemc + OFF_B1S);
    float* v_s  = (float*)(smemc + OFF_VS);
    float* u_s  = (float*)(smemc + OFF_US);
    for (int i = tid; i < H_DIM; i += 128) { b1_s[i] = b1[i]; v_s[i] = g_v[i]; }
    if (tid < 64) u_s[tid] = 0.f;

    float    cacc[2][8][4];                // main, fp32
    uint32_t c16[2][8][2];                 // correction, fp16x2 pairs
#pragma unroll
    for (int i = 0; i < 2; i++)
#pragma unroll
        for (int j = 0; j < 8; j++) {
#pragma unroll
            for (int r = 0; r < 4; r++) cacc[i][j][r] = 0.f;
            c16[i][j][0] = 0u; c16[i][j][1] = 0u;
        }

    fill_chunk(sm, 0, rowBase, 0, tid); CP_COMMIT();
    fill_chunk(sm, 1, rowBase, 1, tid); CP_COMMIT();

    for (int idx = 0; idx < 128; idx++) {
        if (idx >= 126) { CP_WAIT0(); } else { CP_WAIT1(); }
        __syncthreads();
        const uint32_t base = sm + (idx & 1) * BUFSZ;
        const uint32_t aBase = base + (mw * 32) * ROWB;
        const uint32_t bBase = base + ATILE + (nw * 64) * ROWB;
#pragma unroll
        for (int ks = 0; ks < 2; ks++) {
            const uint32_t aAddr = aBase + (lane & 15) * ROWB + ((lane >> 4) * 16) + ks * 32;
            uint32_t ah[2][4];
            ldsm_x4(ah[0][0], ah[0][1], ah[0][2], ah[0][3], aAddr);
            ldsm_x4(ah[1][0], ah[1][1], ah[1][2], ah[1][3], aAddr + 16 * ROWB);
            const uint32_t bAddr0 = bBase + ((lane & 7) + ((lane >> 4) << 3)) * ROWB
                                    + (((lane >> 3) & 1) * 16) + ks * 32;
#pragma unroll
            for (int jj = 0; jj < 4; jj++) {
                uint32_t bh[4], bl[4];
                ldsm_x4(bh[0], bh[1], bh[2], bh[3], bAddr0 + jj * 16 * ROWB);
                ldsm_x4(bl[0], bl[1], bl[2], bl[3], bAddr0 + jj * 16 * ROWB + BTILE);
#pragma unroll
                for (int i = 0; i < 2; i++) {
                    mma16816f(cacc[i][2 * jj],     ah[i], bh[0], bh[1]);
                    mma16816f(cacc[i][2 * jj + 1], ah[i], bh[2], bh[3]);
                    mma16816h(c16[i][2 * jj],      ah[i], bl[0], bl[1]);
                    mma16816h(c16[i][2 * jj + 1],  ah[i], bl[2], bl[3]);
                }
            }
        }
        __syncthreads();
        if (idx + 2 < 128) { fill_chunk(sm, idx & 1, rowBase, idx + 2, tid); CP_COMMIT(); }

        if ((idx & 15) == 15) {
            const int nt = idx >> 4;
#pragma unroll
            for (int i = 0; i < 2; i++) {
                float s0 = 0.f, s1 = 0.f;
#pragma unroll
                for (int j = 0; j < 8; j++) {
                    const int col = nt * 128 + nw * 64 + j * 8 + (lane & 3) * 2;
                    const float bb0 = b1_s[col], bb1 = b1_s[col + 1];
                    const float vv0 = v_s[col], vv1 = v_s[col + 1];
                    const float2 cr01 = __half22float2(*(const __half2*)&c16[i][j][0]);
                    const float2 cr23 = __half22float2(*(const __half2*)&c16[i][j][1]);
                    const float h0 = cacc[i][j][0] + cr01.x * LO_INV + bb0;
                    const float h1 = cacc[i][j][1] + cr01.y * LO_INV + bb1;
                    const float h2 = cacc[i][j][2] + cr23.x * LO_INV + bb0;
                    const float h3 = cacc[i][j][3] + cr23.y * LO_INV + bb1;
                    s0 += fmaxf(h0, 0.f) * vv0 + fmaxf(h1, 0.f) * vv1;
                    s1 += fmaxf(h2, 0.f) * vv0 + fmaxf(h3, 0.f) * vv1;
                    cacc[i][j][0] = cacc[i][j][1] = cacc[i][j][2] = cacc[i][j][3] = 0.f;
                    c16[i][j][0] = 0u; c16[i][j][1] = 0u;
                }
                s0 += __shfl_xor_sync(0xffffffffu, s0, 1);
                s0 += __shfl_xor_sync(0xffffffffu, s0, 2);
                s1 += __shfl_xor_sync(0xffffffffu, s1, 1);
                s1 += __shfl_xor_sync(0xffffffffu, s1, 2);
                if ((lane & 3) == 0) {
                    const int row0 = mw * 32 + i * 16 + (lane >> 2);
                    atomicAdd(&u_s[row0], s0);
                    atomicAdd(&u_s[row0 + 8], s1);
                }
            }
        }
    }
    __syncthreads();
    if (tid < 64) g_u[rowBase + tid] = u_s[tid] + g_c;
}

// ============================================================
// gt: G = A^T A (128x128), t = A^T u. grid 64 x 256 thr (1024 rows/block:
// 4x fewer global atomics than grid 256, same FLOPs).
// ============================================================
__global__ __launch_bounds__(256) void gt_kernel(const float* __restrict__ A) {
    __shared__ float As[32][132];
    __shared__ float u_s[32];
    const int tid = threadIdx.x;
    const int tx = tid & 15;
    const int ty = tid >> 4;

    unsigned long long acc[8][4];
#pragma unroll
    for (int i = 0; i < 8; i++)
#pragma unroll
        for (int j = 0; j < 4; j++) acc[i][j] = 0ull;
    float t_loc = 0.f;

    const int base = blockIdx.x * 1024;
    for (int ch = 0; ch < 32; ch++) {
        const int r0 = base + ch * 32;
        __syncthreads();
#pragma unroll
        for (int rr = 0; rr < 4; rr++) {
            int row = (tid >> 5) + rr * 8;
            *(float4*)&As[row][(tid & 31) * 4] =
                *(const float4*)&A[(size_t)(r0 + row) * S_DIM + (tid & 31) * 4];
        }
        if (tid < 32) u_s[tid] = g_u[r0 + tid];
        __syncthreads();

#pragma unroll 4
        for (int r = 0; r < 32; r++) {
            float4 a0 = *(const float4*)&As[r][ty * 8];
            float4 a1 = *(const float4*)&As[r][ty * 8 + 4];
            unsigned long long a2[8];
            a2[0] = pack2(a0.x, a0.x); a2[1] = pack2(a0.y, a0.y);
            a2[2] = pack2(a0.z, a0.z); a2[3] = pack2(a0.w, a0.w);
            a2[4] = pack2(a1.x, a1.x); a2[5] = pack2(a1.y, a1.y);
            a2[6] = pack2(a1.z, a1.z); a2[7] = pack2(a1.w, a1.w);
            const ulonglong2* bp = (const ulonglong2*)&As[r][tx * 8];
            ulonglong2 bb0 = bp[0];
            ulonglong2 bb1 = bp[1];
            unsigned long long bv[4] = {bb0.x, bb0.y, bb1.x, bb1.y};
#pragma unroll
            for (int i = 0; i < 8; i++)
#pragma unroll
                for (int j = 0; j < 4; j++)
                    acc[i][j] = fma2(a2[i], bv[j], acc[i][j]);
        }
        if (tid < 128) {
#pragma unroll 8
            for (int r = 0; r < 32; r++) t_loc += As[r][tid] * u_s[r];
        }
    }

#pragma unroll
    for (int i = 0; i < 8; i++)
#pragma unroll
        for (int j = 0; j < 4; j++) {
            float lo, hi;
            unpack2(acc[i][j], lo, hi);
            atomicAdd(&g_G[(ty * 8 + i) * S_DIM + tx * 8 + 2 * j], lo);
            atomicAdd(&g_G[(ty * 8 + i) * S_DIM + tx * 8 + 2 * j + 1], hi);
        }
    if (tid < 128) atomicAdd(&g_t[tid], t_loc);
}

// ============================================================
// solve: G y = t via Jacobi (rho ~ 0.09 for this Wishart), 24 iters.
// G staged to smem ONCE (coalesced); inner reads use symmetry
// G[tid][j] == G[j][tid] so Gs[j*128+tid] is coalesced/conflict-free.
// wp = w_struct - y.
// ============================================================
#define SOLVE_SMEM (S_DIM * S_DIM * 4)
__global__ __launch_bounds__(128) void solve_kernel(const float* __restrict__ w_struct) {
    extern __shared__ float Gs[];          // 64 KB
    __shared__ float ys[S_DIM];
    const int tid = threadIdx.x;
    for (int i = tid; i < S_DIM * S_DIM; i += 128) Gs[i] = g_G[i];
    const float tv = g_t[tid];
    __syncthreads();
    const float dinv = 1.0f / Gs[tid * S_DIM + tid];
    ys[tid] = tv * dinv;
    __syncthreads();
    for (int it = 0; it < 24; it++) {
        float s = 0.f;
#pragma unroll 16
        for (int j = 0; j < S_DIM; j++) s += Gs[j * S_DIM + tid] * ys[j];
        const float r = (tv - s) * dinv;
        __syncthreads();
        ys[tid] += r;
        __syncthreads();
    }
    g_wp[tid] = w_struct[tid] - ys[tid];
}

// ============================================================
// final: out[i] = u[i] + A[i,:] . wp
// ============================================================
__global__ __launch_bounds__(256) void final_kernel(const float* __restrict__ A,
                                                    float* __restrict__ out) {
    __shared__ float wp_s[S_DIM];
    const int tid = threadIdx.x;
    if (tid < S_DIM) wp_s[tid] = g_wp[tid];
    __syncthreads();
    const int i = blockIdx.x * 256 + tid;
    const float4* ar = (const float4*)&A[(size_t)i * S_DIM];
    float s = g_u[i];
#pragma unroll
    for (int q = 0; q < 32; q++) {
        float4 a = ar[q];
        s += a.x * wp_s[4 * q] + a.y * wp_s[4 * q + 1] +
             a.z * wp_s[4 * q + 2] + a.w * wp_s[4 * q + 3];
    }
    out[i] = s;
}

// ============================================================
extern "C" void kernel_launch(void* const* d_in, const int* in_sizes, int n_in,
                              void* d_out, int out_size) {
    const float* structured = (const float*)d_in[0];
    const float* d1         = (const float*)d_in[1];
    const float* W1         = (const float*)d_in[2];
    const float* b1         = (const float*)d_in[3];
    const float* W2         = (const float*)d_in[4];
    const float* b2         = (const float*)d_in[5];
    const float* w_struct   = (const float*)d_in[6];
    const float* w_deep     = (const float*)d_in[7];
    float* out = (float*)d_out;

    cudaFuncSetAttribute(mlp_mma_kernel, cudaFuncAttributeMaxDynamicSharedMemorySize,
                         MLP_SMEM);
    cudaFuncSetAttribute(solve_kernel, cudaFuncAttributeMaxDynamicSharedMemorySize,
                         SOLVE_SMEM);

    prep_kernel<<<1, 256>>>(W2, b2, w_deep);
    convert_w1_kernel<<<dim3(DIN / 32, H_DIM / 32), 256>>>(W1);
    convert_d1_kernel<<<(N_ROWS * DIN / 8) / 256, 256>>>(d1);
    mlp_mma_kernel<<<N_ROWS / 64, 128, MLP_SMEM>>>(b1);
    gt_kernel<<<N_ROWS / 1024, 256>>>(structured);
    solve_kernel<<<1, 128, SOLVE_SMEM>>>(w_struct);
    final_kernel<<<N_ROWS / 256, 256>>>(structured, out);
}